// round 1
// baseline (speedup 1.0000x reference)
#include <cuda_runtime.h>
#include <math.h>
#include <stdint.h>

#ifndef M_PI
#define M_PI 3.14159265358979323846
#endif

// Problem shape (fixed by setup_inputs)
#define BB 2
#define NV 4
#define HH 256
#define WW 512
#define HWSZ (HH * WW)            // 131072
#define PP (NV * HWSZ)            // 524288 points per batch
#define TOTAL (BB * PP)           // 1048576 points total
#define NCH 24                    // feat channels

#define VOXEL_SIZE 0.1f
#define CONF_W 0.7f
#define OPAC_W 0.3f
#define CONF_THRESH 0.1f
#define OPAC_THRESH 0.01f

#define TABLE_BITS 22
#define TABLE_SIZE (1u << TABLE_BITS)
#define TABLE_MASK (TABLE_SIZE - 1u)
#define EMPTY_KEY 0xFFFFFFFFu
#define INV_SLOT 0xFFFFFFFFu

// Scratch (no runtime allocation allowed -> __device__ globals)
__device__ unsigned int       g_keys[TABLE_SIZE];
__device__ unsigned long long g_max1[TABLE_SIZE];
__device__ unsigned long long g_max2[TABLE_SIZE];
__device__ unsigned int       g_slot[TOTAL];
__device__ unsigned long long g_pack[TOTAL];

// ---------------------------------------------------------------------------

__global__ void clear_kernel() {
    unsigned i = blockIdx.x * blockDim.x + threadIdx.x;
    if (i < TABLE_SIZE) {
        g_keys[i] = EMPTY_KEY;
        g_max1[i] = 0ull;
        g_max2[i] = 0ull;
    }
}

// Compute mean / validity / voxel key / packed (score, index) key for point g.
__device__ __forceinline__ void compute_point(
    int g, const float* __restrict__ depth, const float* __restrict__ opac,
    const float* __restrict__ conf, const float* __restrict__ poses,
    bool& valid, unsigned& key, unsigned long long& packed,
    float& mx, float& my, float& mz)
{
    int b  = g / PP;
    int p  = g - b * PP;
    int n  = p / HWSZ;
    int hw = p - n * HWSZ;
    int h  = hw / WW;
    int w  = hw - h * WW;

    float d = depth[g];
    float c = conf[g];
    float o = opac[g];
    valid = (c > CONF_THRESH) && (o > OPAC_THRESH);

    // ERP direction (img_h=HH, img_w=WW)
    const float fx = (float)((double)WW / (2.0 * M_PI));
    const float fy = (float)(-(double)HH / M_PI);
    float lon = ((float)w + 0.5f - (float)(WW / 2)) / fx;
    float lat = ((float)h + 0.5f - (float)(HH / 2)) / fy;
    float slat, clat, slon, clon;
    sincosf(lat, &slat, &clat);
    sincosf(lon, &slon, &clon);
    float dx = clat * slon;
    float dy = -slat;
    float dz = clat * clon;

    float px = d * dx, py = d * dy, pz = d * dz;

    const float* M = poses + (size_t)(b * NV + n) * 16;
    mx = M[0] * px + M[1] * py + M[2]  * pz + M[3];
    my = M[4] * px + M[5] * py + M[6]  * pz + M[7];
    mz = M[8] * px + M[9] * py + M[10] * pz + M[11];

    int vx = min(max((int)floorf(mx / VOXEL_SIZE) + 512, 0), 1023);
    int vy = min(max((int)floorf(my / VOXEL_SIZE) + 512, 0), 1023);
    int vz = min(max((int)floorf(mz / VOXEL_SIZE) + 512, 0), 1023);
    unsigned vid = ((unsigned)vx << 20) | ((unsigned)vy << 10) | (unsigned)vz;
    key = ((unsigned)b << 30) | vid;

    float score = CONF_W * c + OPAC_W * o;   // in (0,1): positive -> bit-monotonic
    // Higher score better; ties -> smaller index better (stable-sort semantics).
    packed = ((unsigned long long)__float_as_uint(score) << 32)
           | (unsigned long long)(0xFFFFFFFFu - (unsigned)p);
}

__global__ void pass1_kernel(const float* __restrict__ depth,
                             const float* __restrict__ opac,
                             const float* __restrict__ conf,
                             const float* __restrict__ poses)
{
    int g = blockIdx.x * blockDim.x + threadIdx.x;
    if (g >= TOTAL) return;

    bool valid; unsigned key; unsigned long long packed;
    float mx, my, mz;
    compute_point(g, depth, opac, conf, poses, valid, key, packed, mx, my, mz);

    if (!valid) { g_slot[g] = INV_SLOT; return; }

    unsigned h = (key * 2654435761u) & TABLE_MASK;
    for (;;) {
        unsigned cur = g_keys[h];
        if (cur == key) break;
        if (cur == EMPTY_KEY) {
            unsigned prev = atomicCAS(&g_keys[h], EMPTY_KEY, key);
            if (prev == EMPTY_KEY || prev == key) break;
            // slot stolen by another key: fall through to advance
        }
        h = (h + 1u) & TABLE_MASK;
    }
    atomicMax(&g_max1[h], packed);
    g_slot[g] = h;
    g_pack[g] = packed;
}

__global__ void pass2_kernel() {
    int g = blockIdx.x * blockDim.x + threadIdx.x;
    if (g >= TOTAL) return;
    unsigned slot = g_slot[g];
    if (slot == INV_SLOT) return;
    unsigned long long pk = g_pack[g];
    if (pk != g_max1[slot])
        atomicMax(&g_max2[slot], pk);
}

__global__ void pass3_kernel(const float* __restrict__ depth,
                             const float* __restrict__ cov,
                             const float* __restrict__ rot,
                             const float* __restrict__ opac,
                             const float* __restrict__ sh,
                             const float* __restrict__ conf,
                             const float* __restrict__ poses,
                             float* __restrict__ out,
                             int write_sel, size_t sel_off)
{
    int g = blockIdx.x * blockDim.x + threadIdx.x;
    if (g >= TOTAL) return;

    float s = 0.0f;
    unsigned slot = g_slot[g];
    if (slot != INV_SLOT) {
        unsigned long long pk = g_pack[g];
        if (pk == g_max1[slot] || pk == g_max2[slot]) s = 1.0f;
    }

    bool valid; unsigned key; unsigned long long packed;
    float mx, my, mz;
    compute_point(g, depth, opac, conf, poses, valid, key, packed, mx, my, mz);

    int b  = g / PP;
    int p  = g - b * PP;
    int n  = p / HWSZ;
    int hw = p - n * HWSZ;

    size_t bn     = (size_t)(b * NV + n);
    size_t base_c = (bn * 3)  * HWSZ + hw;
    size_t base_r = (bn * 4)  * HWSZ + hw;
    size_t base_s = (bn * 12) * HWSZ + hw;

    float f[NCH];
    f[0] = mx; f[1] = my; f[2] = mz;
    f[3] = cov[base_c];
    f[4] = cov[base_c + HWSZ];
    f[5] = cov[base_c + 2 * (size_t)HWSZ];
#pragma unroll
    for (int i = 0; i < 4; i++)
        f[6 + i] = rot[base_r + (size_t)i * HWSZ];
    f[10] = opac[g];
#pragma unroll
    for (int i = 0; i < 12; i++)
        f[11 + i] = sh[base_s + (size_t)i * HWSZ];
    f[23] = conf[g];

#pragma unroll
    for (int i = 0; i < NCH; i++) f[i] *= s;

    // 24 floats = 96 B, 16B aligned -> 6x float4 stores
    float4* dst = reinterpret_cast<float4*>(out + (size_t)g * NCH);
#pragma unroll
    for (int i = 0; i < 6; i++) {
        dst[i] = make_float4(f[4 * i], f[4 * i + 1], f[4 * i + 2], f[4 * i + 3]);
    }

    if (write_sel)
        out[sel_off + (size_t)g] = s;
}

// ---------------------------------------------------------------------------

extern "C" void kernel_launch(void* const* d_in, const int* in_sizes, int n_in,
                              void* d_out, int out_size) {
    const float* depth = (const float*)d_in[0];
    const float* cov   = (const float*)d_in[1];
    const float* rot   = (const float*)d_in[2];
    const float* opac  = (const float*)d_in[3];
    const float* sh    = (const float*)d_in[4];
    const float* conf  = (const float*)d_in[5];
    const float* poses = (const float*)d_in[6];
    float* out = (float*)d_out;

    size_t featN = (size_t)TOTAL * NCH;
    int write_sel = ((size_t)out_size >= featN + (size_t)TOTAL) ? 1 : 0;

    const int T = 256;
    clear_kernel<<<(TABLE_SIZE + T - 1) / T, T>>>();
    pass1_kernel<<<(TOTAL + T - 1) / T, T>>>(depth, opac, conf, poses);
    pass2_kernel<<<(TOTAL + T - 1) / T, T>>>();
    pass3_kernel<<<(TOTAL + T - 1) / T, T>>>(depth, cov, rot, opac, sh, conf,
                                             poses, out, write_sel, featN);
}

// round 2
// speedup vs baseline: 1.0605x; 1.0605x over previous
#include <cuda_runtime.h>
#include <math.h>
#include <stdint.h>

#ifndef M_PI
#define M_PI 3.14159265358979323846
#endif

// Problem shape (fixed by setup_inputs)
#define BB 2
#define NV 4
#define HH 256
#define WW 512
#define HWSZ (HH * WW)            // 131072
#define PP (NV * HWSZ)            // 524288 points per batch
#define TOTAL (BB * PP)           // 1048576 points total
#define NCH 24

#define VOXEL_SIZE 0.1f
#define CONF_W 0.7f
#define OPAC_W 0.3f
#define CONF_THRESH 0.1f
#define OPAC_THRESH 0.01f

#define TABLE_BITS 21
#define TABLE_SIZE (1u << TABLE_BITS)
#define TABLE_MASK (TABLE_SIZE - 1u)
#define EMPTY_KEY 0xFFFFFFFFu
#define INV_SLOT 0xFFFFFFFFu

// Scratch (no runtime allocation allowed -> __device__ globals)
__device__ unsigned int g_keys[TABLE_SIZE];          // 8 MB
__device__ ulonglong2   g_pair[TABLE_SIZE];          // 32 MB: {max1, max2}
__device__ unsigned int g_slot[TOTAL];               // 4 MB

// ---------------------------------------------------------------------------

__device__ __forceinline__ ulonglong2 cas128(ulonglong2* addr,
                                             ulonglong2 cmp, ulonglong2 val) {
    ulonglong2 old;
    asm volatile(
        "{\n\t"
        ".reg .b128 c, v, o;\n\t"
        "mov.b128 c, {%2, %3};\n\t"
        "mov.b128 v, {%4, %5};\n\t"
        "atom.relaxed.gpu.global.cas.b128 o, [%6], c, v;\n\t"
        "mov.b128 {%0, %1}, o;\n\t"
        "}"
        : "=l"(old.x), "=l"(old.y)
        : "l"(cmp.x), "l"(cmp.y), "l"(val.x), "l"(val.y), "l"(addr)
        : "memory");
    return old;
}

__global__ void __launch_bounds__(256) clear_kernel() {
    unsigned i = (blockIdx.x * blockDim.x + threadIdx.x) * 4u;
    if (i < TABLE_SIZE) {
        *reinterpret_cast<uint4*>(g_keys + i) =
            make_uint4(EMPTY_KEY, EMPTY_KEY, EMPTY_KEY, EMPTY_KEY);
        ulonglong2 z; z.x = 0ull; z.y = 0ull;
        g_pair[i]     = z;
        g_pair[i + 1] = z;
        g_pair[i + 2] = z;
        g_pair[i + 3] = z;
    }
}

// Insert packed key into voxel `key`'s top-2 pair; returns table slot.
__device__ __forceinline__ unsigned insert_top2(unsigned key,
                                                unsigned long long pk) {
    unsigned h = (key * 2654435761u) >> (32 - TABLE_BITS);
    for (;;) {
        unsigned cur = g_keys[h];
        if (cur == key) break;
        if (cur == EMPTY_KEY) {
            unsigned prev = atomicCAS(&g_keys[h], EMPTY_KEY, key);
            if (prev == EMPTY_KEY || prev == key) break;
        }
        h = (h + 1u) & TABLE_MASK;
    }
    ulonglong2* addr = &g_pair[h];
    ulonglong2 cur = *addr;            // torn read harmless: CAS validates
    while (pk > cur.y) {               // pk unique -> strict compare is exact
        ulonglong2 nw;
        if (pk > cur.x) { nw.x = pk;    nw.y = cur.x; }
        else            { nw.x = cur.x; nw.y = pk;    }
        ulonglong2 prev = cas128(addr, cur, nw);
        if (prev.x == cur.x && prev.y == cur.y) break;
        cur = prev;
    }
    return h;
}

// Identical arithmetic to the R1 passing kernel (keep numerics stable).
__device__ __forceinline__ void compute_point(
    int g, const float* __restrict__ depth, const float* __restrict__ opac,
    const float* __restrict__ conf, const float* __restrict__ poses,
    bool& valid, unsigned& key, unsigned long long& packed,
    float& mx, float& my, float& mz)
{
    int b  = g / PP;
    int p  = g - b * PP;
    int n  = p / HWSZ;
    int hw = p - n * HWSZ;
    int h  = hw / WW;
    int w  = hw - h * WW;

    float d = depth[g];
    float c = conf[g];
    float o = opac[g];
    valid = (c > CONF_THRESH) && (o > OPAC_THRESH);

    const float fx = (float)((double)WW / (2.0 * M_PI));
    const float fy = (float)(-(double)HH / M_PI);
    float lon = ((float)w + 0.5f - (float)(WW / 2)) / fx;
    float lat = ((float)h + 0.5f - (float)(HH / 2)) / fy;
    float slat, clat, slon, clon;
    sincosf(lat, &slat, &clat);
    sincosf(lon, &slon, &clon);
    float dx = clat * slon;
    float dy = -slat;
    float dz = clat * clon;

    float px = d * dx, py = d * dy, pz = d * dz;

    const float* M = poses + (size_t)(b * NV + n) * 16;
    mx = M[0] * px + M[1] * py + M[2]  * pz + M[3];
    my = M[4] * px + M[5] * py + M[6]  * pz + M[7];
    mz = M[8] * px + M[9] * py + M[10] * pz + M[11];

    int vx = min(max((int)floorf(mx / VOXEL_SIZE) + 512, 0), 1023);
    int vy = min(max((int)floorf(my / VOXEL_SIZE) + 512, 0), 1023);
    int vz = min(max((int)floorf(mz / VOXEL_SIZE) + 512, 0), 1023);
    unsigned vid = ((unsigned)vx << 20) | ((unsigned)vy << 10) | (unsigned)vz;
    key = ((unsigned)b << 30) | vid;

    float score = CONF_W * c + OPAC_W * o;
    packed = ((unsigned long long)__float_as_uint(score) << 32)
           | (unsigned long long)(0xFFFFFFFFu - (unsigned)p);
}

// 4 points per thread (one float4 quad per channel; quads never cross a row).
__global__ void __launch_bounds__(256) pass1_kernel(
    const float* __restrict__ depth, const float* __restrict__ opac,
    const float* __restrict__ conf,  const float* __restrict__ poses)
{
    int q = blockIdx.x * blockDim.x + threadIdx.x;
    if (q >= TOTAL / 4) return;
    int g0 = q << 2;

    int b   = g0 / PP;
    int p0  = g0 - b * PP;
    int n   = p0 / HWSZ;
    int hw0 = p0 - n * HWSZ;
    int h   = hw0 / WW;
    int w0  = hw0 - h * WW;

    float4 d4 = *reinterpret_cast<const float4*>(depth + g0);
    float4 c4 = *reinterpret_cast<const float4*>(conf  + g0);
    float4 o4 = *reinterpret_cast<const float4*>(opac  + g0);
    float dd[4] = {d4.x, d4.y, d4.z, d4.w};
    float cc[4] = {c4.x, c4.y, c4.z, c4.w};
    float oo[4] = {o4.x, o4.y, o4.z, o4.w};

    const float fx = (float)((double)WW / (2.0 * M_PI));
    const float fy = (float)(-(double)HH / M_PI);
    float lat = ((float)h + 0.5f - (float)(HH / 2)) / fy;
    float slat, clat;
    sincosf(lat, &slat, &clat);

    const float* M = poses + (size_t)(b * NV + n) * 16;
    float M0 = M[0], M1 = M[1], M2 = M[2],  M3 = M[3];
    float M4 = M[4], M5 = M[5], M6 = M[6],  M7 = M[7];
    float M8 = M[8], M9 = M[9], M10 = M[10], M11 = M[11];

    unsigned slots[4];
#pragma unroll
    for (int k = 0; k < 4; k++) {
        float c = cc[k], o = oo[k], d = dd[k];
        bool valid = (c > CONF_THRESH) && (o > OPAC_THRESH);
        if (!valid) { slots[k] = INV_SLOT; continue; }

        float lon = ((float)(w0 + k) + 0.5f - (float)(WW / 2)) / fx;
        float slon, clon;
        sincosf(lon, &slon, &clon);
        float dx = clat * slon;
        float dy = -slat;
        float dz = clat * clon;
        float px = d * dx, py = d * dy, pz = d * dz;

        float mx = M0 * px + M1 * py + M2  * pz + M3;
        float my = M4 * px + M5 * py + M6  * pz + M7;
        float mz = M8 * px + M9 * py + M10 * pz + M11;

        int vx = min(max((int)floorf(mx / VOXEL_SIZE) + 512, 0), 1023);
        int vy = min(max((int)floorf(my / VOXEL_SIZE) + 512, 0), 1023);
        int vz = min(max((int)floorf(mz / VOXEL_SIZE) + 512, 0), 1023);
        unsigned vid = ((unsigned)vx << 20) | ((unsigned)vy << 10) | (unsigned)vz;
        unsigned key = ((unsigned)b << 30) | vid;

        float score = CONF_W * c + OPAC_W * o;
        unsigned p = (unsigned)(p0 + k);
        unsigned long long pk =
            ((unsigned long long)__float_as_uint(score) << 32)
            | (unsigned long long)(0xFFFFFFFFu - p);

        slots[k] = insert_top2(key, pk);
    }
    *reinterpret_cast<uint4*>(g_slot + g0) =
        make_uint4(slots[0], slots[1], slots[2], slots[3]);
}

__global__ void __launch_bounds__(256) pass3_kernel(
    const float* __restrict__ depth, const float* __restrict__ cov,
    const float* __restrict__ rot,   const float* __restrict__ opac,
    const float* __restrict__ sh,    const float* __restrict__ conf,
    const float* __restrict__ poses, float* __restrict__ out,
    int write_sel, size_t sel_off)
{
    int g = blockIdx.x * blockDim.x + threadIdx.x;
    if (g >= TOTAL) return;

    bool valid; unsigned key; unsigned long long packed;
    float mx, my, mz;
    compute_point(g, depth, opac, conf, poses, valid, key, packed, mx, my, mz);

    float s = 0.0f;
    unsigned slot = g_slot[g];
    if (slot != INV_SLOT) {
        ulonglong2 pr = g_pair[slot];
        if (packed == pr.x || packed == pr.y) s = 1.0f;
    }

    int b  = g / PP;
    int p  = g - b * PP;
    int n  = p / HWSZ;
    int hw = p - n * HWSZ;

    size_t bn     = (size_t)(b * NV + n);
    size_t base_c = (bn * 3)  * HWSZ + hw;
    size_t base_r = (bn * 4)  * HWSZ + hw;
    size_t base_s = (bn * 12) * HWSZ + hw;

    float f[NCH];
    f[0] = mx; f[1] = my; f[2] = mz;
    f[3] = __ldcs(&cov[base_c]);
    f[4] = __ldcs(&cov[base_c + HWSZ]);
    f[5] = __ldcs(&cov[base_c + 2 * (size_t)HWSZ]);
#pragma unroll
    for (int i = 0; i < 4; i++)
        f[6 + i] = __ldcs(&rot[base_r + (size_t)i * HWSZ]);
    f[10] = opac[g];
#pragma unroll
    for (int i = 0; i < 12; i++)
        f[11 + i] = __ldcs(&sh[base_s + (size_t)i * HWSZ]);
    f[23] = conf[g];

#pragma unroll
    for (int i = 0; i < NCH; i++) f[i] *= s;

    float4* dst = reinterpret_cast<float4*>(out + (size_t)g * NCH);
#pragma unroll
    for (int i = 0; i < 6; i++)
        __stcs(dst + i, make_float4(f[4*i], f[4*i+1], f[4*i+2], f[4*i+3]));

    if (write_sel)
        __stcs(out + sel_off + (size_t)g, s);
}

// ---------------------------------------------------------------------------

extern "C" void kernel_launch(void* const* d_in, const int* in_sizes, int n_in,
                              void* d_out, int out_size) {
    const float* depth = (const float*)d_in[0];
    const float* cov   = (const float*)d_in[1];
    const float* rot   = (const float*)d_in[2];
    const float* opac  = (const float*)d_in[3];
    const float* sh    = (const float*)d_in[4];
    const float* conf  = (const float*)d_in[5];
    const float* poses = (const float*)d_in[6];
    float* out = (float*)d_out;

    size_t featN = (size_t)TOTAL * NCH;
    int write_sel = ((size_t)out_size >= featN + (size_t)TOTAL) ? 1 : 0;

    const int T = 256;
    clear_kernel<<<(TABLE_SIZE / 4 + T - 1) / T, T>>>();
    pass1_kernel<<<(TOTAL / 4 + T - 1) / T, T>>>(depth, opac, conf, poses);
    pass3_kernel<<<(TOTAL + T - 1) / T, T>>>(depth, cov, rot, opac, sh, conf,
                                             poses, out, write_sel, featN);
}

// round 3
// speedup vs baseline: 1.0639x; 1.0033x over previous
#include <cuda_runtime.h>
#include <math.h>
#include <stdint.h>

#ifndef M_PI
#define M_PI 3.14159265358979323846
#endif

// Problem shape (fixed by setup_inputs)
#define BB 2
#define NV 4
#define HH 256
#define WW 512
#define HWSZ (HH * WW)            // 131072
#define PP (NV * HWSZ)            // 524288 points per batch
#define TOTAL (BB * PP)           // 1048576 points total
#define NCH 24

#define VOXEL_SIZE 0.1f
#define CONF_W 0.7f
#define OPAC_W 0.3f
#define CONF_THRESH 0.1f
#define OPAC_THRESH 0.01f

#define TABLE_BITS 21
#define TABLE_SIZE (1u << TABLE_BITS)
#define TABLE_MASK (TABLE_SIZE - 1u)
#define EMPTY_KEY 0xFFFFFFFFu
#define INV_SLOT 0xFFFFFFFFu

// Scratch (no runtime allocation allowed -> __device__ globals)
__device__ unsigned int g_keys[TABLE_SIZE];          // 8 MB
__device__ ulonglong2   g_pair[TABLE_SIZE];          // 32 MB: {max1, max2}
__device__ unsigned int g_slot[TOTAL];               // 4 MB

// ---------------------------------------------------------------------------

__device__ __forceinline__ ulonglong2 cas128(ulonglong2* addr,
                                             ulonglong2 cmp, ulonglong2 val) {
    ulonglong2 old;
    asm volatile(
        "{\n\t"
        ".reg .b128 c, v, o;\n\t"
        "mov.b128 c, {%2, %3};\n\t"
        "mov.b128 v, {%4, %5};\n\t"
        "atom.relaxed.gpu.global.cas.b128 o, [%6], c, v;\n\t"
        "mov.b128 {%0, %1}, o;\n\t"
        "}"
        : "=l"(old.x), "=l"(old.y)
        : "l"(cmp.x), "l"(cmp.y), "l"(val.x), "l"(val.y), "l"(addr)
        : "memory");
    return old;
}

// One 16-byte store per thread; massive grid so LSU issue never serializes.
#define KEYS16 (TABLE_SIZE / 4)              // uint4 chunks covering g_keys
#define CLEAR16 (KEYS16 + TABLE_SIZE)        // + ulonglong2 chunks for g_pair
__global__ void __launch_bounds__(256) clear_kernel() {
    unsigned i = blockIdx.x * blockDim.x + threadIdx.x;
    if (i < KEYS16) {
        reinterpret_cast<uint4*>(g_keys)[i] =
            make_uint4(EMPTY_KEY, EMPTY_KEY, EMPTY_KEY, EMPTY_KEY);
    } else if (i < CLEAR16) {
        ulonglong2 z; z.x = 0ull; z.y = 0ull;
        g_pair[i - KEYS16] = z;
    }
}

// Insert packed key into voxel `key`'s top-2 pair; returns table slot.
__device__ __forceinline__ unsigned insert_top2(unsigned key,
                                                unsigned long long pk) {
    unsigned h = (key * 2654435761u) >> (32 - TABLE_BITS);
    for (;;) {
        unsigned cur = g_keys[h];
        if (cur == key) break;
        if (cur == EMPTY_KEY) {
            unsigned prev = atomicCAS(&g_keys[h], EMPTY_KEY, key);
            if (prev == EMPTY_KEY || prev == key) break;
        }
        h = (h + 1u) & TABLE_MASK;
    }
    ulonglong2* addr = &g_pair[h];
    ulonglong2 cur = *addr;            // torn read harmless: CAS validates
    while (pk > cur.y) {               // pk unique -> strict compare is exact
        ulonglong2 nw;
        if (pk > cur.x) { nw.x = pk;    nw.y = cur.x; }
        else            { nw.x = cur.x; nw.y = pk;    }
        ulonglong2 prev = cas128(addr, cur, nw);
        if (prev.x == cur.x && prev.y == cur.y) break;
        cur = prev;
    }
    return h;
}

// Identical arithmetic to the R1 passing kernel (keep numerics stable).
__device__ __forceinline__ void compute_point(
    int g, const float* __restrict__ depth, const float* __restrict__ opac,
    const float* __restrict__ conf, const float* __restrict__ poses,
    bool& valid, unsigned& key, unsigned long long& packed,
    float& mx, float& my, float& mz)
{
    int b  = g / PP;
    int p  = g - b * PP;
    int n  = p / HWSZ;
    int hw = p - n * HWSZ;
    int h  = hw / WW;
    int w  = hw - h * WW;

    float d = depth[g];
    float c = conf[g];
    float o = opac[g];
    valid = (c > CONF_THRESH) && (o > OPAC_THRESH);

    const float fx = (float)((double)WW / (2.0 * M_PI));
    const float fy = (float)(-(double)HH / M_PI);
    float lon = ((float)w + 0.5f - (float)(WW / 2)) / fx;
    float lat = ((float)h + 0.5f - (float)(HH / 2)) / fy;
    float slat, clat, slon, clon;
    sincosf(lat, &slat, &clat);
    sincosf(lon, &slon, &clon);
    float dx = clat * slon;
    float dy = -slat;
    float dz = clat * clon;

    float px = d * dx, py = d * dy, pz = d * dz;

    const float* M = poses + (size_t)(b * NV + n) * 16;
    mx = M[0] * px + M[1] * py + M[2]  * pz + M[3];
    my = M[4] * px + M[5] * py + M[6]  * pz + M[7];
    mz = M[8] * px + M[9] * py + M[10] * pz + M[11];

    int vx = min(max((int)floorf(mx / VOXEL_SIZE) + 512, 0), 1023);
    int vy = min(max((int)floorf(my / VOXEL_SIZE) + 512, 0), 1023);
    int vz = min(max((int)floorf(mz / VOXEL_SIZE) + 512, 0), 1023);
    unsigned vid = ((unsigned)vx << 20) | ((unsigned)vy << 10) | (unsigned)vz;
    key = ((unsigned)b << 30) | vid;

    float score = CONF_W * c + OPAC_W * o;
    packed = ((unsigned long long)__float_as_uint(score) << 32)
           | (unsigned long long)(0xFFFFFFFFu - (unsigned)p);
}

// 4 points per thread (one float4 quad per channel; quads never cross a row).
__global__ void __launch_bounds__(256) pass1_kernel(
    const float* __restrict__ depth, const float* __restrict__ opac,
    const float* __restrict__ conf,  const float* __restrict__ poses)
{
    int q = blockIdx.x * blockDim.x + threadIdx.x;
    if (q >= TOTAL / 4) return;
    int g0 = q << 2;

    int b   = g0 / PP;
    int p0  = g0 - b * PP;
    int n   = p0 / HWSZ;
    int hw0 = p0 - n * HWSZ;
    int h   = hw0 / WW;
    int w0  = hw0 - h * WW;

    float4 d4 = *reinterpret_cast<const float4*>(depth + g0);
    float4 c4 = *reinterpret_cast<const float4*>(conf  + g0);
    float4 o4 = *reinterpret_cast<const float4*>(opac  + g0);
    float dd[4] = {d4.x, d4.y, d4.z, d4.w};
    float cc[4] = {c4.x, c4.y, c4.z, c4.w};
    float oo[4] = {o4.x, o4.y, o4.z, o4.w};

    const float fx = (float)((double)WW / (2.0 * M_PI));
    const float fy = (float)(-(double)HH / M_PI);
    float lat = ((float)h + 0.5f - (float)(HH / 2)) / fy;
    float slat, clat;
    sincosf(lat, &slat, &clat);

    const float* M = poses + (size_t)(b * NV + n) * 16;
    float M0 = M[0], M1 = M[1], M2 = M[2],  M3 = M[3];
    float M4 = M[4], M5 = M[5], M6 = M[6],  M7 = M[7];
    float M8 = M[8], M9 = M[9], M10 = M[10], M11 = M[11];

    unsigned slots[4];
#pragma unroll
    for (int k = 0; k < 4; k++) {
        float c = cc[k], o = oo[k], d = dd[k];
        bool valid = (c > CONF_THRESH) && (o > OPAC_THRESH);
        if (!valid) { slots[k] = INV_SLOT; continue; }

        float lon = ((float)(w0 + k) + 0.5f - (float)(WW / 2)) / fx;
        float slon, clon;
        sincosf(lon, &slon, &clon);
        float dx = clat * slon;
        float dy = -slat;
        float dz = clat * clon;
        float px = d * dx, py = d * dy, pz = d * dz;

        float mx = M0 * px + M1 * py + M2  * pz + M3;
        float my = M4 * px + M5 * py + M6  * pz + M7;
        float mz = M8 * px + M9 * py + M10 * pz + M11;

        int vx = min(max((int)floorf(mx / VOXEL_SIZE) + 512, 0), 1023);
        int vy = min(max((int)floorf(my / VOXEL_SIZE) + 512, 0), 1023);
        int vz = min(max((int)floorf(mz / VOXEL_SIZE) + 512, 0), 1023);
        unsigned vid = ((unsigned)vx << 20) | ((unsigned)vy << 10) | (unsigned)vz;
        unsigned key = ((unsigned)b << 30) | vid;

        float score = CONF_W * c + OPAC_W * o;
        unsigned p = (unsigned)(p0 + k);
        unsigned long long pk =
            ((unsigned long long)__float_as_uint(score) << 32)
            | (unsigned long long)(0xFFFFFFFFu - p);

        slots[k] = insert_top2(key, pk);
    }
    *reinterpret_cast<uint4*>(g_slot + g0) =
        make_uint4(slots[0], slots[1], slots[2], slots[3]);
}

// Output staged through shared memory so the 96B/point rows are flushed with
// perfectly coalesced float4 stores (1 L1 wavefront per STG instead of ~24).
__global__ void __launch_bounds__(256) pass3_kernel(
    const float* __restrict__ depth, const float* __restrict__ cov,
    const float* __restrict__ rot,   const float* __restrict__ opac,
    const float* __restrict__ sh,    const float* __restrict__ conf,
    const float* __restrict__ poses, float* __restrict__ out,
    int write_sel, size_t sel_off)
{
    __shared__ float sbuf[256 * NCH];          // 24 KB

    int tid = threadIdx.x;
    int g = blockIdx.x * 256 + tid;            // grid sized exactly TOTAL/256

    bool valid; unsigned key; unsigned long long packed;
    float mx, my, mz;
    compute_point(g, depth, opac, conf, poses, valid, key, packed, mx, my, mz);

    float s = 0.0f;
    unsigned slot = g_slot[g];
    if (slot != INV_SLOT) {
        ulonglong2 pr = g_pair[slot];
        if (packed == pr.x || packed == pr.y) s = 1.0f;
    }

    int b  = g / PP;
    int p  = g - b * PP;
    int n  = p / HWSZ;
    int hw = p - n * HWSZ;

    size_t bn     = (size_t)(b * NV + n);
    size_t base_c = (bn * 3)  * HWSZ + hw;
    size_t base_r = (bn * 4)  * HWSZ + hw;
    size_t base_s = (bn * 12) * HWSZ + hw;

    float f[NCH];
    f[0] = mx; f[1] = my; f[2] = mz;
    f[3] = __ldcs(&cov[base_c]);
    f[4] = __ldcs(&cov[base_c + HWSZ]);
    f[5] = __ldcs(&cov[base_c + 2 * (size_t)HWSZ]);
#pragma unroll
    for (int i = 0; i < 4; i++)
        f[6 + i] = __ldcs(&rot[base_r + (size_t)i * HWSZ]);
    f[10] = opac[g];
#pragma unroll
    for (int i = 0; i < 12; i++)
        f[11 + i] = __ldcs(&sh[base_s + (size_t)i * HWSZ]);
    f[23] = conf[g];

#pragma unroll
    for (int i = 0; i < NCH; i++) f[i] *= s;

    // Stage this point's row in smem (STS.128 x6, 16B-aligned since 24%4==0).
    float4* srow = reinterpret_cast<float4*>(sbuf + tid * NCH);
#pragma unroll
    for (int i = 0; i < 6; i++)
        srow[i] = make_float4(f[4*i], f[4*i+1], f[4*i+2], f[4*i+3]);

    __syncthreads();

    // Coalesced flush: 1536 float4s by 256 threads = 6 iters.
    const float4* src = reinterpret_cast<const float4*>(sbuf);
    float4* dst = reinterpret_cast<float4*>(out + (size_t)blockIdx.x * 256 * NCH);
#pragma unroll
    for (int it = 0; it < 6; it++) {
        int j = it * 256 + tid;
        __stcs(dst + j, src[j]);
    }

    if (write_sel)
        __stcs(out + sel_off + (size_t)g, s);
}

// ---------------------------------------------------------------------------

extern "C" void kernel_launch(void* const* d_in, const int* in_sizes, int n_in,
                              void* d_out, int out_size) {
    const float* depth = (const float*)d_in[0];
    const float* cov   = (const float*)d_in[1];
    const float* rot   = (const float*)d_in[2];
    const float* opac  = (const float*)d_in[3];
    const float* sh    = (const float*)d_in[4];
    const float* conf  = (const float*)d_in[5];
    const float* poses = (const float*)d_in[6];
    float* out = (float*)d_out;

    size_t featN = (size_t)TOTAL * NCH;
    int write_sel = ((size_t)out_size >= featN + (size_t)TOTAL) ? 1 : 0;

    const int T = 256;
    clear_kernel<<<(CLEAR16 + T - 1) / T, T>>>();
    pass1_kernel<<<(TOTAL / 4 + T - 1) / T, T>>>(depth, opac, conf, poses);
    pass3_kernel<<<TOTAL / T, T>>>(depth, cov, rot, opac, sh, conf,
                                   poses, out, write_sel, featN);
}

// round 4
// speedup vs baseline: 1.3558x; 1.2743x over previous
#include <cuda_runtime.h>
#include <math.h>
#include <stdint.h>

#ifndef M_PI
#define M_PI 3.14159265358979323846
#endif

// Problem shape (fixed by setup_inputs)
#define BB 2
#define NV 4
#define HH 256
#define WW 512
#define HWSZ (HH * WW)            // 131072
#define PP (NV * HWSZ)            // 524288 points per batch
#define TOTAL (BB * PP)           // 1048576 points total
#define NCH 24

#define VOXEL_SIZE 0.1f
#define CONF_W 0.7f
#define OPAC_W 0.3f
#define CONF_THRESH 0.1f
#define OPAC_THRESH 0.01f

#define TABLE_BITS 21
#define TABLE_SIZE (1u << TABLE_BITS)
#define TABLE_MASK (TABLE_SIZE - 1u)
#define EMPTY_KEY 0xFFFFFFFFu
#define INV_SLOT 0xFFFFFFFFu

// Scratch (no runtime allocation allowed -> __device__ globals)
__device__ unsigned int       g_keys[TABLE_SIZE];   // 8 MB
__device__ unsigned long long g_max1[TABLE_SIZE];   // 16 MB
__device__ unsigned long long g_max2[TABLE_SIZE];   // 16 MB
__device__ unsigned int       g_slot[TOTAL];        // 4 MB

// ---------------------------------------------------------------------------

// One 16-byte store per thread; large grid so LSU issue never serializes.
#define KEYS16  (TABLE_SIZE / 4)                    // uint4 chunks for g_keys
#define MAX16   (TABLE_SIZE / 2)                    // ulonglong2 chunks per max array
#define CLEAR16 (KEYS16 + 2 * MAX16)
__global__ void __launch_bounds__(256) clear_kernel() {
    unsigned i = blockIdx.x * blockDim.x + threadIdx.x;
    if (i < KEYS16) {
        reinterpret_cast<uint4*>(g_keys)[i] =
            make_uint4(EMPTY_KEY, EMPTY_KEY, EMPTY_KEY, EMPTY_KEY);
    } else if (i < KEYS16 + MAX16) {
        ulonglong2 z; z.x = 0ull; z.y = 0ull;
        reinterpret_cast<ulonglong2*>(g_max1)[i - KEYS16] = z;
    } else if (i < CLEAR16) {
        ulonglong2 z; z.x = 0ull; z.y = 0ull;
        reinterpret_cast<ulonglong2*>(g_max2)[i - (KEYS16 + MAX16)] = z;
    }
}

// Find (or claim) the table slot for voxel `key`.
__device__ __forceinline__ unsigned probe_slot(unsigned key) {
    unsigned h = (key * 2654435761u) >> (32 - TABLE_BITS);
    for (;;) {
        unsigned cur = g_keys[h];
        if (cur == key) return h;
        if (cur == EMPTY_KEY) {
            unsigned prev = atomicCAS(&g_keys[h], EMPTY_KEY, key);
            if (prev == EMPTY_KEY || prev == key) return h;
        }
        h = (h + 1u) & TABLE_MASK;
    }
}

// Identical arithmetic to the R1 passing kernel (keep numerics stable).
__device__ __forceinline__ void compute_point(
    int g, const float* __restrict__ depth, const float* __restrict__ opac,
    const float* __restrict__ conf, const float* __restrict__ poses,
    bool& valid, unsigned& key, unsigned long long& packed,
    float& mx, float& my, float& mz)
{
    int b  = g / PP;
    int p  = g - b * PP;
    int n  = p / HWSZ;
    int hw = p - n * HWSZ;
    int h  = hw / WW;
    int w  = hw - h * WW;

    float d = depth[g];
    float c = conf[g];
    float o = opac[g];
    valid = (c > CONF_THRESH) && (o > OPAC_THRESH);

    const float fx = (float)((double)WW / (2.0 * M_PI));
    const float fy = (float)(-(double)HH / M_PI);
    float lon = ((float)w + 0.5f - (float)(WW / 2)) / fx;
    float lat = ((float)h + 0.5f - (float)(HH / 2)) / fy;
    float slat, clat, slon, clon;
    sincosf(lat, &slat, &clat);
    sincosf(lon, &slon, &clon);
    float dx = clat * slon;
    float dy = -slat;
    float dz = clat * clon;

    float px = d * dx, py = d * dy, pz = d * dz;

    const float* M = poses + (size_t)(b * NV + n) * 16;
    mx = M[0] * px + M[1] * py + M[2]  * pz + M[3];
    my = M[4] * px + M[5] * py + M[6]  * pz + M[7];
    mz = M[8] * px + M[9] * py + M[10] * pz + M[11];

    int vx = min(max((int)floorf(mx / VOXEL_SIZE) + 512, 0), 1023);
    int vy = min(max((int)floorf(my / VOXEL_SIZE) + 512, 0), 1023);
    int vz = min(max((int)floorf(mz / VOXEL_SIZE) + 512, 0), 1023);
    unsigned vid = ((unsigned)vx << 20) | ((unsigned)vy << 10) | (unsigned)vz;
    key = ((unsigned)b << 30) | vid;

    float score = CONF_W * c + OPAC_W * o;
    packed = ((unsigned long long)__float_as_uint(score) << 32)
           | (unsigned long long)(0xFFFFFFFFu - (unsigned)p);
}

// Streaming top-2: one atomicMax with return + one fire-and-forget RED.MAX.
// Every value except the running max is attempted into max2, so after all
// inserts max2 == second maximum. No CAS retry loops, 1 point per thread so
// the L2 atomic latency chains overlap across warps.
__global__ void __launch_bounds__(256) pass1_kernel(
    const float* __restrict__ depth, const float* __restrict__ opac,
    const float* __restrict__ conf,  const float* __restrict__ poses)
{
    int g = blockIdx.x * blockDim.x + threadIdx.x;
    if (g >= TOTAL) return;

    bool valid; unsigned key; unsigned long long pk;
    float mx, my, mz;
    compute_point(g, depth, opac, conf, poses, valid, key, pk, mx, my, mz);

    if (!valid) { g_slot[g] = INV_SLOT; return; }

    unsigned slot = probe_slot(key);
    unsigned long long old = atomicMax(&g_max1[slot], pk);
    unsigned long long v = (pk < old) ? pk : old;   // displaced value
    if (v != 0ull)
        atomicMax(&g_max2[slot], v);                // result unused -> RED

    g_slot[g] = slot;
}

__global__ void __launch_bounds__(256) pass3_kernel(
    const float* __restrict__ depth, const float* __restrict__ cov,
    const float* __restrict__ rot,   const float* __restrict__ opac,
    const float* __restrict__ sh,    const float* __restrict__ conf,
    const float* __restrict__ poses, float* __restrict__ out,
    int write_sel, size_t sel_off)
{
    int g = blockIdx.x * blockDim.x + threadIdx.x;
    if (g >= TOTAL) return;

    bool valid; unsigned key; unsigned long long packed;
    float mx, my, mz;
    compute_point(g, depth, opac, conf, poses, valid, key, packed, mx, my, mz);

    float s = 0.0f;
    unsigned slot = g_slot[g];
    if (slot != INV_SLOT) {
        if (packed == g_max1[slot] || packed == g_max2[slot]) s = 1.0f;
    }

    int b  = g / PP;
    int p  = g - b * PP;
    int n  = p / HWSZ;
    int hw = p - n * HWSZ;

    size_t bn     = (size_t)(b * NV + n);
    size_t base_c = (bn * 3)  * HWSZ + hw;
    size_t base_r = (bn * 4)  * HWSZ + hw;
    size_t base_s = (bn * 12) * HWSZ + hw;

    float f[NCH];
    f[0] = mx; f[1] = my; f[2] = mz;
    f[3] = __ldcs(&cov[base_c]);
    f[4] = __ldcs(&cov[base_c + HWSZ]);
    f[5] = __ldcs(&cov[base_c + 2 * (size_t)HWSZ]);
#pragma unroll
    for (int i = 0; i < 4; i++)
        f[6 + i] = __ldcs(&rot[base_r + (size_t)i * HWSZ]);
    f[10] = opac[g];
#pragma unroll
    for (int i = 0; i < 12; i++)
        f[11 + i] = __ldcs(&sh[base_s + (size_t)i * HWSZ]);
    f[23] = conf[g];

#pragma unroll
    for (int i = 0; i < NCH; i++) f[i] *= s;

    float4* dst = reinterpret_cast<float4*>(out + (size_t)g * NCH);
#pragma unroll
    for (int i = 0; i < 6; i++)
        __stcs(dst + i, make_float4(f[4*i], f[4*i+1], f[4*i+2], f[4*i+3]));

    if (write_sel)
        __stcs(out + sel_off + (size_t)g, s);
}

// ---------------------------------------------------------------------------

extern "C" void kernel_launch(void* const* d_in, const int* in_sizes, int n_in,
                              void* d_out, int out_size) {
    const float* depth = (const float*)d_in[0];
    const float* cov   = (const float*)d_in[1];
    const float* rot   = (const float*)d_in[2];
    const float* opac  = (const float*)d_in[3];
    const float* sh    = (const float*)d_in[4];
    const float* conf  = (const float*)d_in[5];
    const float* poses = (const float*)d_in[6];
    float* out = (float*)d_out;

    size_t featN = (size_t)TOTAL * NCH;
    int write_sel = ((size_t)out_size >= featN + (size_t)TOTAL) ? 1 : 0;

    const int T = 256;
    clear_kernel<<<(CLEAR16 + T - 1) / T, T>>>();
    pass1_kernel<<<(TOTAL + T - 1) / T, T>>>(depth, opac, conf, poses);
    pass3_kernel<<<(TOTAL + T - 1) / T, T>>>(depth, cov, rot, opac, sh, conf,
                                             poses, out, write_sel, featN);
}